// round 5
// baseline (speedup 1.0000x reference)
#include <cuda_runtime.h>
#include <math.h>

#define NB   4
#define SEQ  4096
#define DIM  256
#define NH   4
#define HD   64
#define MTOT (NB * SEQ)        // 16384
#define QK_SCALE 0.125f        // 64^-0.5

// Scratch (allocation-free rule: __device__ globals)
static __device__ float g_q[NB * NH * SEQ * HD];   // [B,H,S,Hd]
static __device__ float g_k[NB * NH * SEQ * HD];
static __device__ float g_v[NB * NH * SEQ * HD];
static __device__ float g_o[MTOT * DIM];           // [B,S,D] attention output

// ---------------------------------------------------------------------------
// QKV projection: C[m,n] = sum_k x[m,k] * W[n,k]   (W is [out,in] row-major)
// blockIdx.z selects (wq->g_q, wk->g_k, wv->g_v); output written head-split.
// 64x64 tile, 256 threads, 4x4 micro-tile, K-tile 16.
// ---------------------------------------------------------------------------
__global__ __launch_bounds__(256) void qkv_proj_kernel(
    const float* __restrict__ x,
    const float* __restrict__ wq,
    const float* __restrict__ wk,
    const float* __restrict__ wv)
{
    const int z = blockIdx.z;
    const float* __restrict__ W = (z == 0) ? wq : (z == 1) ? wk : wv;
    float* __restrict__ out     = (z == 0) ? g_q : (z == 1) ? g_k : g_v;

    __shared__ float As[64][17];
    __shared__ float Bs[64][17];

    const int m0  = blockIdx.y * 64;
    const int n0  = blockIdx.x * 64;
    const int tid = threadIdx.x;
    const int tx  = tid & 15;   // 0..15 -> n micro
    const int ty  = tid >> 4;   // 0..15 -> m micro

    const int lrow = tid >> 2;          // 0..63
    const int lq   = (tid & 3) * 4;     // 0,4,8,12

    float acc[4][4] = {};

    for (int k0 = 0; k0 < DIM; k0 += 16) {
        float4 av = *(const float4*)(x + (size_t)(m0 + lrow) * DIM + k0 + lq);
        float4 bv = *(const float4*)(W + (size_t)(n0 + lrow) * DIM + k0 + lq);
        As[lrow][lq + 0] = av.x; As[lrow][lq + 1] = av.y;
        As[lrow][lq + 2] = av.z; As[lrow][lq + 3] = av.w;
        Bs[lrow][lq + 0] = bv.x; Bs[lrow][lq + 1] = bv.y;
        Bs[lrow][lq + 2] = bv.z; Bs[lrow][lq + 3] = bv.w;
        __syncthreads();

        #pragma unroll
        for (int k = 0; k < 16; ++k) {
            float a[4], b[4];
            #pragma unroll
            for (int i = 0; i < 4; ++i) a[i] = As[ty * 4 + i][k];
            #pragma unroll
            for (int j = 0; j < 4; ++j) b[j] = Bs[tx * 4 + j][k];
            #pragma unroll
            for (int i = 0; i < 4; ++i)
                #pragma unroll
                for (int j = 0; j < 4; ++j)
                    acc[i][j] += a[i] * b[j];
        }
        __syncthreads();
    }

    // Epilogue: head-split layout [B,H,S,Hd]
    #pragma unroll
    for (int i = 0; i < 4; ++i) {
        const int m = m0 + ty * 4 + i;
        const int b = m >> 12;          // /SEQ
        const int s = m & (SEQ - 1);
        #pragma unroll
        for (int j = 0; j < 4; ++j) {
            const int n = n0 + tx * 4 + j;
            const int h = n >> 6;       // /HD
            const int d = n & (HD - 1);
            out[(((size_t)b * NH + h) * SEQ + s) * HD + d] = acc[i][j];
        }
    }
}

// ---------------------------------------------------------------------------
// Flash attention: one (b,h) per blockIdx.y, 128 query rows per block
// (1 thread per row). q & acc in registers; KV tiles of 32 in SMEM.
// Lazy-rescale online softmax (no per-tile score array -> no spills).
// Writes g_o in [B,S,D] layout so the output projection is a plain GEMM.
// ---------------------------------------------------------------------------
__global__ __launch_bounds__(128) void attn_kernel()
{
    const int bh   = blockIdx.y;                  // b*NH + h
    const int qrow = blockIdx.x * 128 + threadIdx.x;
    const int tid  = threadIdx.x;

    const float* __restrict__ Qb = g_q + (size_t)bh * SEQ * HD;
    const float* __restrict__ Kb = g_k + (size_t)bh * SEQ * HD;
    const float* __restrict__ Vb = g_v + (size_t)bh * SEQ * HD;

    __shared__ float Ks[32][HD];   // 8 KB
    __shared__ float Vs[32][HD];   // 8 KB

    // q row -> registers (16 float4)
    float4 q4[16];
    {
        const float4* qg = (const float4*)(Qb + (size_t)qrow * HD);
        #pragma unroll
        for (int d = 0; d < 16; ++d) q4[d] = qg[d];
    }

    float4 acc4[16];
    #pragma unroll
    for (int d = 0; d < 16; ++d) acc4[d] = make_float4(0.f, 0.f, 0.f, 0.f);
    float m = -1e30f;
    float l = 0.f;

    for (int kt = 0; kt < SEQ; kt += 32) {
        __syncthreads();   // previous tile fully consumed
        {
            const float4* Kg = (const float4*)(Kb + (size_t)kt * HD);
            const float4* Vg = (const float4*)(Vb + (size_t)kt * HD);
            float4* Ks4 = (float4*)Ks;
            float4* Vs4 = (float4*)Vs;
            #pragma unroll
            for (int i = tid; i < 512; i += 128) {   // 32*64 floats = 512 float4
                Ks4[i] = Kg[i];
                Vs4[i] = Vg[i];
            }
        }
        __syncthreads();

        #pragma unroll 1
        for (int j = 0; j < 32; ++j) {
            // score = SCALE * dot(q, K[j])  (broadcast LDS.128, conflict-free)
            const float4* kr = (const float4*)Ks[j];
            float s = 0.f;
            #pragma unroll
            for (int d = 0; d < 16; ++d) {
                const float4 kk = kr[d];
                s += q4[d].x * kk.x + q4[d].y * kk.y
                   + q4[d].z * kk.z + q4[d].w * kk.w;
            }
            s *= QK_SCALE;

            if (s > m) {                    // rare: ~ln(S) times per row
                const float corr = __expf(m - s);
                l *= corr;
                #pragma unroll
                for (int d = 0; d < 16; ++d) {
                    acc4[d].x *= corr; acc4[d].y *= corr;
                    acc4[d].z *= corr; acc4[d].w *= corr;
                }
                m = s;
            }
            const float p = __expf(s - m);
            l += p;

            const float4* vr = (const float4*)Vs[j];
            #pragma unroll
            for (int d = 0; d < 16; ++d) {
                const float4 vv = vr[d];
                acc4[d].x += p * vv.x; acc4[d].y += p * vv.y;
                acc4[d].z += p * vv.z; acc4[d].w += p * vv.w;
            }
        }
    }

    // write out in [B,S,D] layout
    const float inv_l = 1.0f / l;
    const int b = bh >> 2;          // /NH
    const int h = bh & (NH - 1);
    float4* og = (float4*)(g_o + ((size_t)(b * SEQ + qrow)) * DIM + h * HD);
    #pragma unroll
    for (int d = 0; d < 16; ++d) {
        float4 v = acc4[d];
        v.x *= inv_l; v.y *= inv_l; v.z *= inv_l; v.w *= inv_l;
        og[d] = v;
    }
}

// ---------------------------------------------------------------------------
// Output projection: Y[m,n] = sum_k g_o[m,k] * wo[n,k] + bo[n]
// ---------------------------------------------------------------------------
__global__ __launch_bounds__(256) void out_proj_kernel(
    const float* __restrict__ wo,
    const float* __restrict__ bo,
    float* __restrict__ Y)
{
    __shared__ float As[64][17];
    __shared__ float Bs[64][17];

    const int m0  = blockIdx.y * 64;
    const int n0  = blockIdx.x * 64;
    const int tid = threadIdx.x;
    const int tx  = tid & 15;
    const int ty  = tid >> 4;

    const int lrow = tid >> 2;
    const int lq   = (tid & 3) * 4;

    float acc[4][4] = {};

    for (int k0 = 0; k0 < DIM; k0 += 16) {
        float4 av = *(const float4*)(g_o + (size_t)(m0 + lrow) * DIM + k0 + lq);
        float4 bv = *(const float4*)(wo  + (size_t)(n0 + lrow) * DIM + k0 + lq);
        As[lrow][lq + 0] = av.x; As[lrow][lq + 1] = av.y;
        As[lrow][lq + 2] = av.z; As[lrow][lq + 3] = av.w;
        Bs[lrow][lq + 0] = bv.x; Bs[lrow][lq + 1] = bv.y;
        Bs[lrow][lq + 2] = bv.z; Bs[lrow][lq + 3] = bv.w;
        __syncthreads();

        #pragma unroll
        for (int k = 0; k < 16; ++k) {
            float a[4], b[4];
            #pragma unroll
            for (int i = 0; i < 4; ++i) a[i] = As[ty * 4 + i][k];
            #pragma unroll
            for (int j = 0; j < 4; ++j) b[j] = Bs[tx * 4 + j][k];
            #pragma unroll
            for (int i = 0; i < 4; ++i)
                #pragma unroll
                for (int j = 0; j < 4; ++j)
                    acc[i][j] += a[i] * b[j];
        }
        __syncthreads();
    }

    #pragma unroll
    for (int i = 0; i < 4; ++i) {
        const int m = m0 + ty * 4 + i;
        #pragma unroll
        for (int j = 0; j < 4; ++j) {
            const int n = n0 + tx * 4 + j;
            Y[(size_t)m * DIM + n] = acc[i][j] + bo[n];
        }
    }
}

// ---------------------------------------------------------------------------
extern "C" void kernel_launch(void* const* d_in, const int* in_sizes, int n_in,
                              void* d_out, int out_size)
{
    const float* x  = (const float*)d_in[0];
    const float* wq = (const float*)d_in[1];
    const float* wk = (const float*)d_in[2];
    const float* wv = (const float*)d_in[3];
    const float* wo = (const float*)d_in[4];
    const float* bo = (const float*)d_in[5];
    float* out = (float*)d_out;

    dim3 g1(DIM / 64, MTOT / 64, 3);       // 4 x 256 x 3
    qkv_proj_kernel<<<g1, 256>>>(x, wq, wk, wv);

    dim3 g2(SEQ / 128, NB * NH);           // 32 x 16
    attn_kernel<<<g2, 128>>>();

    dim3 g3(DIM / 64, MTOT / 64);          // 4 x 256
    out_proj_kernel<<<g3, 256>>>(wo, bo, out);
}

// round 10
// speedup vs baseline: 3.6847x; 3.6847x over previous
#include <cuda_runtime.h>
#include <stdint.h>
#include <math.h>

#define NB   4
#define SEQ  4096
#define DIM  256
#define NH   4
#define HD   64
#define MTOT (NB * SEQ)        // 16384
#define QK_SCALE 0.125f        // 64^-0.5

// Scratch (allocation-free rule: __device__ globals)
static __device__ float g_q[NB * NH * SEQ * HD];   // [B,H,S,Hd]
static __device__ float g_k[NB * NH * SEQ * HD];
static __device__ float g_v[NB * NH * SEQ * HD];
static __device__ float g_o[MTOT * DIM];           // [B,S,D] attention output

// ---------------------------------------------------------------------------
// Helpers: tf32 convert (round-to-nearest!), fast exp2, warp mma m16n8k8 tf32
// ---------------------------------------------------------------------------
__device__ __forceinline__ float f2tf32(float x) {
    unsigned int r;
    asm("cvt.rna.tf32.f32 %0, %1;" : "=r"(r) : "f"(x));
    return __uint_as_float(r);
}
__device__ __forceinline__ unsigned int f2tf32u(float x) {
    unsigned int r;
    asm("cvt.rna.tf32.f32 %0, %1;" : "=r"(r) : "f"(x));
    return r;
}
__device__ __forceinline__ float ex2f(float x) {
    float y;
    asm("ex2.approx.f32 %0, %1;" : "=f"(y) : "f"(x));
    return y;
}
__device__ __forceinline__ void mma_tf32(float* c, const unsigned int* a,
                                         unsigned int b0, unsigned int b1) {
    asm volatile(
        "mma.sync.aligned.m16n8k8.row.col.f32.tf32.tf32.f32 "
        "{%0,%1,%2,%3}, {%4,%5,%6,%7}, {%8,%9}, {%0,%1,%2,%3};"
        : "+f"(c[0]), "+f"(c[1]), "+f"(c[2]), "+f"(c[3])
        : "r"(a[0]), "r"(a[1]), "r"(a[2]), "r"(a[3]), "r"(b0), "r"(b1));
}

// ---------------------------------------------------------------------------
// QKV projection (exact fp32): C[m,n] = sum_k x[m,k] * W[n,k]
// ---------------------------------------------------------------------------
__global__ __launch_bounds__(256) void qkv_proj_kernel(
    const float* __restrict__ x,
    const float* __restrict__ wq,
    const float* __restrict__ wk,
    const float* __restrict__ wv)
{
    const int z = blockIdx.z;
    const float* __restrict__ W = (z == 0) ? wq : (z == 1) ? wk : wv;
    float* __restrict__ out     = (z == 0) ? g_q : (z == 1) ? g_k : g_v;

    __shared__ float As[64][17];
    __shared__ float Bs[64][17];

    const int m0  = blockIdx.y * 64;
    const int n0  = blockIdx.x * 64;
    const int tid = threadIdx.x;
    const int tx  = tid & 15;
    const int ty  = tid >> 4;
    const int lrow = tid >> 2;
    const int lq   = (tid & 3) * 4;

    float acc[4][4] = {};

    for (int k0 = 0; k0 < DIM; k0 += 16) {
        float4 av = *(const float4*)(x + (size_t)(m0 + lrow) * DIM + k0 + lq);
        float4 bv = *(const float4*)(W + (size_t)(n0 + lrow) * DIM + k0 + lq);
        As[lrow][lq + 0] = av.x; As[lrow][lq + 1] = av.y;
        As[lrow][lq + 2] = av.z; As[lrow][lq + 3] = av.w;
        Bs[lrow][lq + 0] = bv.x; Bs[lrow][lq + 1] = bv.y;
        Bs[lrow][lq + 2] = bv.z; Bs[lrow][lq + 3] = bv.w;
        __syncthreads();

        #pragma unroll
        for (int k = 0; k < 16; ++k) {
            float a[4], b[4];
            #pragma unroll
            for (int i = 0; i < 4; ++i) a[i] = As[ty * 4 + i][k];
            #pragma unroll
            for (int j = 0; j < 4; ++j) b[j] = Bs[tx * 4 + j][k];
            #pragma unroll
            for (int i = 0; i < 4; ++i)
                #pragma unroll
                for (int j = 0; j < 4; ++j)
                    acc[i][j] += a[i] * b[j];
        }
        __syncthreads();
    }

    #pragma unroll
    for (int i = 0; i < 4; ++i) {
        const int m = m0 + ty * 4 + i;
        const int b = m >> 12;
        const int s = m & (SEQ - 1);
        #pragma unroll
        for (int j = 0; j < 4; ++j) {
            const int n = n0 + tx * 4 + j;
            const int h = n >> 6;
            const int d = n & (HD - 1);
            out[(((size_t)b * NH + h) * SEQ + s) * HD + d] = acc[i][j];
        }
    }
}

// ---------------------------------------------------------------------------
// Flash attention with tf32 tensor-core MMA.
//   CTA: 128 q-rows, 4 warps; each warp owns m32 (two m16 tiles).
//   Key tile Kc=32. K/V staged in SMEM (tf32-rounded), P via per-warp SMEM.
//   SMEM pads: K ld=68 (QK B-frag conflict-free), V ld=72 (PV B-frag
//   conflict-free), P ld=36 (A-frag conflict-free).
// ---------------------------------------------------------------------------
#define KC   32
#define LDK  68
#define LDV  72
#define LDP  36

__global__ __launch_bounds__(128, 2) void attn_mma_kernel()
{
    const int bh   = blockIdx.y;
    const int tid  = threadIdx.x;
    const int warp = tid >> 5;
    const int lane = tid & 31;
    const int qg   = lane >> 2;   // group id 0..7 (row within tile)
    const int qt   = lane & 3;    // thread-in-quad 0..3 (col selector)

    const float* __restrict__ Qb = g_q + (size_t)bh * SEQ * HD;
    const float* __restrict__ Kb = g_k + (size_t)bh * SEQ * HD;
    const float* __restrict__ Vb = g_v + (size_t)bh * SEQ * HD;

    __shared__ float Ks[KC * LDK];            //  8.5 KB
    __shared__ float Vs[KC * LDV];            //  9.0 KB
    __shared__ float Ps[4][32 * LDP];         // 18.0 KB (per-warp P buffer)

    const int row0 = blockIdx.x * 128 + warp * 32;   // warp's first q row

    // ---- Q fragments (tf32) in registers: [mt][kk][4] ----
    unsigned int qa[2][8][4];
    #pragma unroll
    for (int mt = 0; mt < 2; ++mt) {
        const int r = row0 + mt * 16;
        #pragma unroll
        for (int kk = 0; kk < 8; ++kk) {
            const int c = kk * 8 + qt;
            qa[mt][kk][0] = f2tf32u(Qb[(size_t)(r + qg    ) * HD + c    ]);
            qa[mt][kk][1] = f2tf32u(Qb[(size_t)(r + qg + 8) * HD + c    ]);
            qa[mt][kk][2] = f2tf32u(Qb[(size_t)(r + qg    ) * HD + c + 4]);
            qa[mt][kk][3] = f2tf32u(Qb[(size_t)(r + qg + 8) * HD + c + 4]);
        }
    }

    // ---- O accumulators + softmax state ----
    float o[2][8][4];
    #pragma unroll
    for (int mt = 0; mt < 2; ++mt)
        #pragma unroll
        for (int nn = 0; nn < 8; ++nn)
            #pragma unroll
            for (int j = 0; j < 4; ++j) o[mt][nn][j] = 0.f;

    float mrow[2][2] = {{-1e30f, -1e30f}, {-1e30f, -1e30f}};
    float lrow[2][2] = {{0.f, 0.f}, {0.f, 0.f}};

    const float cs = QK_SCALE * 1.44269504f;  // fold scale into exp2
    float* Pw = Ps[warp];

    for (int kt = 0; kt < SEQ; kt += KC) {
        __syncthreads();   // previous tile (K/V) fully consumed

        // ---- stage K,V tile -> SMEM with tf32 rounding ----
        #pragma unroll
        for (int i = tid; i < KC * HD / 4; i += 128) {   // 512 float4
            const int r = i >> 4;
            const int c = (i & 15) << 2;
            float4 k4 = *(const float4*)(Kb + (size_t)(kt + r) * HD + c);
            float4 v4 = *(const float4*)(Vb + (size_t)(kt + r) * HD + c);
            float* kd = Ks + r * LDK + c;
            float* vd = Vs + r * LDV + c;
            kd[0] = f2tf32(k4.x); kd[1] = f2tf32(k4.y);
            kd[2] = f2tf32(k4.z); kd[3] = f2tf32(k4.w);
            vd[0] = f2tf32(v4.x); vd[1] = f2tf32(v4.y);
            vd[2] = f2tf32(v4.z); vd[3] = f2tf32(v4.w);
        }
        __syncthreads();

        // ---- S = Q K^T (raw dot, scaled later inside exp2) ----
        float sacc[2][4][4];
        #pragma unroll
        for (int mt = 0; mt < 2; ++mt)
            #pragma unroll
            for (int nn = 0; nn < 4; ++nn)
                #pragma unroll
                for (int j = 0; j < 4; ++j) sacc[mt][nn][j] = 0.f;

        #pragma unroll
        for (int kk = 0; kk < 8; ++kk) {
            #pragma unroll
            for (int nn = 0; nn < 4; ++nn) {
                // B = K^T: b0=K[key][d], b1=K[key][d+4]; bank = lane (free)
                const int key = nn * 8 + qg;
                const int d   = kk * 8 + qt;
                unsigned int b0 = __float_as_uint(Ks[key * LDK + d    ]);
                unsigned int b1 = __float_as_uint(Ks[key * LDK + d + 4]);
                mma_tf32(sacc[0][nn], qa[0][kk], b0, b1);
                mma_tf32(sacc[1][nn], qa[1][kk], b0, b1);
            }
        }

        // ---- online softmax ----
        float mnew[2][2];
        bool need = false;
        #pragma unroll
        for (int mt = 0; mt < 2; ++mt) {
            #pragma unroll
            for (int h = 0; h < 2; ++h) {
                float mx = sacc[mt][0][2 * h];
                #pragma unroll
                for (int nn = 0; nn < 4; ++nn) {
                    mx = fmaxf(mx, sacc[mt][nn][2 * h]);
                    mx = fmaxf(mx, sacc[mt][nn][2 * h + 1]);
                }
                mx = fmaxf(mx, __shfl_xor_sync(0xffffffffu, mx, 1));
                mx = fmaxf(mx, __shfl_xor_sync(0xffffffffu, mx, 2));
                mnew[mt][h] = fmaxf(mrow[mt][h], mx);
                need |= (mnew[mt][h] > mrow[mt][h]);
            }
        }
        if (__any_sync(0xffffffffu, need)) {
            #pragma unroll
            for (int mt = 0; mt < 2; ++mt) {
                #pragma unroll
                for (int h = 0; h < 2; ++h) {
                    const float sc = ex2f((mrow[mt][h] - mnew[mt][h]) * cs);
                    lrow[mt][h] *= sc;
                    #pragma unroll
                    for (int nn = 0; nn < 8; ++nn) {
                        o[mt][nn][2 * h    ] *= sc;
                        o[mt][nn][2 * h + 1] *= sc;
                    }
                }
            }
        }
        #pragma unroll
        for (int mt = 0; mt < 2; ++mt)
            #pragma unroll
            for (int h = 0; h < 2; ++h) mrow[mt][h] = mnew[mt][h];

        // ---- p = exp2(cs*(s-m)); accumulate l; store tf32 P to SMEM ----
        #pragma unroll
        for (int mt = 0; mt < 2; ++mt) {
            #pragma unroll
            for (int h = 0; h < 2; ++h) {
                const float mh = mnew[mt][h];
                float rs = 0.f;
                const int prow = mt * 16 + h * 8 + qg;
                #pragma unroll
                for (int nn = 0; nn < 4; ++nn) {
                    float p0 = ex2f((sacc[mt][nn][2 * h    ] - mh) * cs);
                    float p1 = ex2f((sacc[mt][nn][2 * h + 1] - mh) * cs);
                    rs += p0 + p1;
                    float2 pv = make_float2(f2tf32(p0), f2tf32(p1));
                    *(float2*)(Pw + prow * LDP + nn * 8 + 2 * qt) = pv;
                }
                rs += __shfl_xor_sync(0xffffffffu, rs, 1);
                rs += __shfl_xor_sync(0xffffffffu, rs, 2);
                lrow[mt][h] += rs;
            }
        }
        __syncwarp();

        // ---- O += P V ----
        #pragma unroll
        for (int kk = 0; kk < 4; ++kk) {
            unsigned int pa[2][4];
            #pragma unroll
            for (int mt = 0; mt < 2; ++mt) {
                const int r = mt * 16 + qg;
                const int c = kk * 8 + qt;
                pa[mt][0] = __float_as_uint(Pw[(r    ) * LDP + c    ]);
                pa[mt][1] = __float_as_uint(Pw[(r + 8) * LDP + c    ]);
                pa[mt][2] = __float_as_uint(Pw[(r    ) * LDP + c + 4]);
                pa[mt][3] = __float_as_uint(Pw[(r + 8) * LDP + c + 4]);
            }
            #pragma unroll
            for (int nn = 0; nn < 8; ++nn) {
                // B = V: b0=V[key][d], key=kk*8+qt(+4), d=nn*8+qg; bank-free
                const int d = nn * 8 + qg;
                unsigned int b0 = __float_as_uint(Vs[(kk * 8 + qt    ) * LDV + d]);
                unsigned int b1 = __float_as_uint(Vs[(kk * 8 + qt + 4) * LDV + d]);
                mma_tf32(o[0][nn], pa[0], b0, b1);
                mma_tf32(o[1][nn], pa[1], b0, b1);
            }
        }
    }

    // ---- write O/l to g_o in [B,S,D] layout ----
    const int b = bh >> 2;
    const int h = bh & (NH - 1);
    #pragma unroll
    for (int mt = 0; mt < 2; ++mt) {
        #pragma unroll
        for (int hf = 0; hf < 2; ++hf) {
            const float inv = 1.0f / lrow[mt][hf];
            const int row = row0 + mt * 16 + hf * 8 + qg;
            float* og = g_o + ((size_t)(b * SEQ + row)) * DIM + h * HD;
            #pragma unroll
            for (int nn = 0; nn < 8; ++nn) {
                float2 v = make_float2(o[mt][nn][2 * hf] * inv,
                                       o[mt][nn][2 * hf + 1] * inv);
                *(float2*)(og + nn * 8 + 2 * qt) = v;
            }
        }
    }
}

// ---------------------------------------------------------------------------
// Output projection (exact fp32): Y = g_o @ wo.T + bo
// ---------------------------------------------------------------------------
__global__ __launch_bounds__(256) void out_proj_kernel(
    const float* __restrict__ wo,
    const float* __restrict__ bo,
    float* __restrict__ Y)
{
    __shared__ float As[64][17];
    __shared__ float Bs[64][17];

    const int m0  = blockIdx.y * 64;
    const int n0  = blockIdx.x * 64;
    const int tid = threadIdx.x;
    const int tx  = tid & 15;
    const int ty  = tid >> 4;
    const int lrow = tid >> 2;
    const int lq   = (tid & 3) * 4;

    float acc[4][4] = {};

    for (int k0 = 0; k0 < DIM; k0 += 16) {
        float4 av = *(const float4*)(g_o + (size_t)(m0 + lrow) * DIM + k0 + lq);
        float4 bv = *(const float4*)(wo  + (size_t)(n0 + lrow) * DIM + k0 + lq);
        As[lrow][lq + 0] = av.x; As[lrow][lq + 1] = av.y;
        As[lrow][lq + 2] = av.z; As[lrow][lq + 3] = av.w;
        Bs[lrow][lq + 0] = bv.x; Bs[lrow][lq + 1] = bv.y;
        Bs[lrow][lq + 2] = bv.z; Bs[lrow][lq + 3] = bv.w;
        __syncthreads();

        #pragma unroll
        for (int k = 0; k < 16; ++k) {
            float a[4], b[4];
            #pragma unroll
            for (int i = 0; i < 4; ++i) a[i] = As[ty * 4 + i][k];
            #pragma unroll
            for (int j = 0; j < 4; ++j) b[j] = Bs[tx * 4 + j][k];
            #pragma unroll
            for (int i = 0; i < 4; ++i)
                #pragma unroll
                for (int j = 0; j < 4; ++j)
                    acc[i][j] += a[i] * b[j];
        }
        __syncthreads();
    }

    #pragma unroll
    for (int i = 0; i < 4; ++i) {
        const int m = m0 + ty * 4 + i;
        #pragma unroll
        for (int j = 0; j < 4; ++j) {
            const int n = n0 + tx * 4 + j;
            Y[(size_t)m * DIM + n] = acc[i][j] + bo[n];
        }
    }
}

// ---------------------------------------------------------------------------
extern "C" void kernel_launch(void* const* d_in, const int* in_sizes, int n_in,
                              void* d_out, int out_size)
{
    const float* x  = (const float*)d_in[0];
    const float* wq = (const float*)d_in[1];
    const float* wk = (const float*)d_in[2];
    const float* wv = (const float*)d_in[3];
    const float* wo = (const float*)d_in[4];
    const float* bo = (const float*)d_in[5];
    float* out = (float*)d_out;

    dim3 g1(DIM / 64, MTOT / 64, 3);
    qkv_proj_kernel<<<g1, 256>>>(x, wq, wk, wv);

    dim3 g2(SEQ / 128, NB * NH);           // 32 x 16
    attn_mma_kernel<<<g2, 128>>>();

    dim3 g3(DIM / 64, MTOT / 64);
    out_proj_kernel<<<g3, 256>>>(wo, bo, out);
}